// round 6
// baseline (speedup 1.0000x reference)
#include <cuda_runtime.h>

#define N_ROWS 2048      // 256 * 8
#define L 128
#define OUT 65
#define OUT2 (OUT * OUT) // 4225
#define THREADS 160
#define EPS 1e-6f

__global__ __launch_bounds__(THREADS) void gasf_kernel(const float* __restrict__ x,
                                                       float* __restrict__ out) {
    __shared__ unsigned ball[4];
    __shared__ float smn[4], smx[4];
    __shared__ float2 scss[OUT];   // (cos, sin) per position

    const int row = blockIdx.x;               // one (n, c) row per block
    const int tid = threadIdx.x;              // 0..159
    const int lane = tid & 31;
    const int warp = tid >> 5;

    const float POS_INF = __int_as_float(0x7f800000);

    // ---- preamble: 128 threads load one element each ----
    float v = 0.0f;
    bool valid = false;
    if (tid < L) {
        v = x[row * L + tid];
        unsigned m = __ballot_sync(0xffffffffu, v != 0.0f);
        if (lane == 0) ball[warp] = m;
    }
    __syncthreads();

    if (tid < L) {
        // first/last nonzero position along L
        int first = L, last = -1;
        unsigned b0 = ball[0], b1 = ball[1], b2 = ball[2], b3 = ball[3];
        if (b0)      first = __ffs(b0) - 1;
        else if (b1) first = 32 + __ffs(b1) - 1;
        else if (b2) first = 64 + __ffs(b2) - 1;
        else if (b3) first = 96 + __ffs(b3) - 1;
        if (b3)      last = 96 + 31 - __clz(b3);
        else if (b2) last = 64 + 31 - __clz(b2);
        else if (b1) last = 32 + 31 - __clz(b1);
        else if (b0) last = 31 - __clz(b0);

        valid = (tid >= first) && (tid <= last);
        float mn = valid ? v : POS_INF;
        float mx = valid ? v : -POS_INF;
        #pragma unroll
        for (int off = 16; off; off >>= 1) {
            mn = fminf(mn, __shfl_xor_sync(0xffffffffu, mn, off));
            mx = fmaxf(mx, __shfl_xor_sync(0xffffffffu, mx, off));
        }
        if (lane == 0) { smn[warp] = mn; smx[warp] = mx; }
    }
    __syncthreads();

    if (tid < OUT) {
        float xmin = fminf(fminf(smn[0], smn[1]), fminf(smn[2], smn[3]));
        float xmax = fmaxf(fmaxf(smx[0], smx[1]), fmaxf(smx[2], smx[3]));
        xmin = fminf(xmin, 0.0f);              // inf (all-invalid) -> 0, clamp <= 0
        xmax = fmaxf(xmax, 0.0f);
        float range = fmaxf(xmax - xmin, EPS);
        float xn = valid ? (2.0f * (v - xmin) / range - 1.0f) : 0.0f;
        float c = fminf(fmaxf(xn, -1.0f + EPS), 1.0f - EPS);
        float s = sqrtf(fmaxf(1.0f - c * c, 0.0f));
        scss[tid] = make_float2(c, s);
    }
    __syncthreads();

    // ---- body: each thread owns one column j, loops over rows i ----
    // tid 0..64   -> g=0, j=tid,    i in [0, 32]   (33 rows)
    // tid 65..129 -> g=1, j=tid-65, i in [33, 64]  (32 rows)
    if (tid < 2 * OUT) {
        const int g = (tid >= OUT) ? 1 : 0;
        const int j = tid - g * OUT;
        const float2 b = scss[j];              // loop-invariant, in registers
        const float nby = -b.y;
        float* p = out + (size_t)row * OUT2 + (g * 33) * OUT + j;
        const float2* ap = &scss[g * 33];

        #pragma unroll
        for (int it = 0; it < 32; ++it) {
            float2 a = ap[it];                 // LDS.64, warp-broadcast, imm offset
            p[it * OUT] = fmaf(a.x, b.x, a.y * nby);  // STG.32, imm offset, coalesced
        }
        if (g == 0) {                          // extra row i=32 for the first group
            float2 a = ap[32];
            p[32 * OUT] = fmaf(a.x, b.x, a.y * nby);
        }
    }
}

extern "C" void kernel_launch(void* const* d_in, const int* in_sizes, int n_in,
                              void* d_out, int out_size) {
    const float* x = (const float*)d_in[0];
    float* out = (float*)d_out;
    gasf_kernel<<<N_ROWS, THREADS>>>(x, out);
}